// round 14
// baseline (speedup 1.0000x reference)
#include <cuda_runtime.h>
#include <cuda_bf16.h>
#include <cstdint>

#define HIDDEN    1024
#define HEADS     16
#define HEAD_DIM  64
#define BATCH     4
#define SEQ       1024
#define ROWS      (BATCH*SEQ)        // 4096
#define BETA_F    0.9f
#define CLAMP_F   1.0f
#define STATE_CAP_F 10.0f
#define PITCH     40                 // ushorts per smem row (80 B, bank-clean)

#define ARR_BYTES    (128*PITCH*2)   // 10240
#define STAGE_BYTES  (4*ARR_BYTES)   // 40960
#define SMEM_TOTAL_B (2*STAGE_BYTES) // 81920

// ---------------- scratch (static device arrays are allowed) ---------------
__device__ float g_q[ROWS*HIDDEN];
__device__ float g_k[ROWS*HIDDEN];
__device__ float g_v[ROWS*HIDDEN];
__device__ float g_state_scratch[BATCH*HEADS*HEAD_DIM*HEAD_DIM];

// pre-split bf16 operands
__device__ __nv_bfloat16 g_Xhi[ROWS*HIDDEN],  g_Xlo[ROWS*HIDDEN];
__device__ __nv_bfloat16 g_Whi[4*HIDDEN*HIDDEN], g_Wlo[4*HIDDEN*HIDDEN]; // q,k,v,o
__device__ __nv_bfloat16 g_Ohi[ROWS*HIDDEN],  g_Olo[ROWS*HIDDEN];

// ---------------------------------------------------------------------------
#define MMA16816(d, a, b0, b1)                                              \
    asm volatile("mma.sync.aligned.m16n8k16.row.col.f32.bf16.bf16.f32 "     \
                 "{%0,%1,%2,%3}, {%4,%5,%6,%7}, {%8,%9}, {%0,%1,%2,%3};"    \
                 : "+f"((d)[0]), "+f"((d)[1]), "+f"((d)[2]), "+f"((d)[3])   \
                 : "r"((a)[0]), "r"((a)[1]), "r"((a)[2]), "r"((a)[3]),      \
                   "r"(b0), "r"(b1))

#define LDSM4(r, addr)                                                      \
    asm volatile("ldmatrix.sync.aligned.m8n8.x4.shared.b16 "                \
                 "{%0,%1,%2,%3}, [%4];"                                     \
                 : "=r"((r)[0]), "=r"((r)[1]), "=r"((r)[2]), "=r"((r)[3])   \
                 : "r"(addr))

#define CP16(dst, src)                                                      \
    asm volatile("cp.async.cg.shared.global [%0], [%1], 16;"                \
                 :: "r"(dst), "l"(src))
#define CP_COMMIT() asm volatile("cp.async.commit_group;")
#define CP_WAIT(n)  asm volatile("cp.async.wait_group %0;" :: "n"(n))

__device__ __forceinline__ void bf16_split1(float x, __nv_bfloat16& h,
                                            __nv_bfloat16& l)
{
    h = __float2bfloat16_rn(x);
    l = __float2bfloat16_rn(x - __bfloat162float(h));
}

// ---------------------------------------------------------------------------
// split fp32 -> bf16 hi/lo. z=0: X; z=1..4: Wq,Wk,Wv,Wo. 8 elems/thread.
// ---------------------------------------------------------------------------
__global__ __launch_bounds__(256) void split_kernel(
    const float* __restrict__ X,  const float* __restrict__ Wq,
    const float* __restrict__ Wk, const float* __restrict__ Wv,
    const float* __restrict__ Wo)
{
    const int z = blockIdx.z;
    const float* src; __nv_bfloat16* hi; __nv_bfloat16* lo; int n8;
    if (z == 0) { src = X;  hi = g_Xhi; lo = g_Xlo; n8 = ROWS*HIDDEN/8; }
    else {
        const float* ws[4] = {Wq, Wk, Wv, Wo};
        src = ws[z-1];
        hi = g_Whi + (size_t)(z-1)*HIDDEN*HIDDEN;
        lo = g_Wlo + (size_t)(z-1)*HIDDEN*HIDDEN;
        n8 = HIDDEN*HIDDEN/8;
    }
    const int i = blockIdx.x * 256 + threadIdx.x;
    if (i >= n8) return;
    const float4* p = (const float4*)src + 2*(size_t)i;
    float4 x0 = p[0], x1 = p[1];
    __nv_bfloat16 h[8], l[8];
    bf16_split1(x0.x, h[0], l[0]); bf16_split1(x0.y, h[1], l[1]);
    bf16_split1(x0.z, h[2], l[2]); bf16_split1(x0.w, h[3], l[3]);
    bf16_split1(x1.x, h[4], l[4]); bf16_split1(x1.y, h[5], l[5]);
    bf16_split1(x1.z, h[6], l[6]); bf16_split1(x1.w, h[7], l[7]);
    *(uint4*)(hi + 8*(size_t)i) = *(uint4*)h;
    *(uint4*)(lo + 8*(size_t)i) = *(uint4*)l;
}

// ---------------------------------------------------------------------------
// bf16x3 tensor-core GEMM (unchanged from R11/R12).
// ---------------------------------------------------------------------------
__device__ __forceinline__ void gemm_bf16_body(
    const __nv_bfloat16* __restrict__ Ahi, const __nv_bfloat16* __restrict__ Alo,
    const __nv_bfloat16* __restrict__ Bhi, const __nv_bfloat16* __restrict__ Blo,
    const float* __restrict__ bias, float* __restrict__ C,
    int m0, int n0, bool norm)
{
    extern __shared__ unsigned short dynsm[];
    const int N = HIDDEN, K = HIDDEN;

    const int tid  = threadIdx.x;
    const int lane = tid & 31;
    const int warp = tid >> 5;
    const int wm   = warp & 3;
    const int wn   = warp >> 2;

    const int arow = tid >> 1;
    const int acol = (tid & 1) * 16;
    const size_t aoff0 = (size_t)(m0 + arow) * K + acol;
    const size_t boff0 = (size_t)(n0 + arow) * K + acol;
    const uint32_t smbase = (uint32_t)__cvta_generic_to_shared(dynsm);
    const uint32_t dst0   = smbase + (uint32_t)(arow * (PITCH*2) + (tid & 1) * 32);

    const int a_row_l = lane & 15;
    const int a_col_l = (lane >> 4) << 3;
    const int b_n_l   = ((lane >> 4) << 3) + (lane & 7);
    const int b_k_l   = ((lane >> 3) & 1) << 3;

    float acc[2][8][4];
#pragma unroll
    for (int mi = 0; mi < 2; mi++)
#pragma unroll
        for (int nj = 0; nj < 8; nj++)
#pragma unroll
            for (int r = 0; r < 4; r++) acc[mi][nj][r] = 0.f;

    {
        const uint32_t d = dst0;
        CP16(d + 0*ARR_BYTES,      Ahi + aoff0);
        CP16(d + 0*ARR_BYTES + 16, Ahi + aoff0 + 8);
        CP16(d + 1*ARR_BYTES,      Alo + aoff0);
        CP16(d + 1*ARR_BYTES + 16, Alo + aoff0 + 8);
        CP16(d + 2*ARR_BYTES,      Bhi + boff0);
        CP16(d + 2*ARR_BYTES + 16, Bhi + boff0 + 8);
        CP16(d + 3*ARR_BYTES,      Blo + boff0);
        CP16(d + 3*ARR_BYTES + 16, Blo + boff0 + 8);
        CP_COMMIT();
    }

    const int NT = K / 32;
    for (int it = 0; it < NT; it++) {
        const int cur = it & 1;
        const int nxt = cur ^ 1;
        const bool hn = (it + 1) < NT;

        if (hn) {
            const int k1 = (it + 1) * 32;
            const uint32_t d = dst0 + nxt * STAGE_BYTES;
            const size_t ao = aoff0 + k1;
            const size_t bo = boff0 + k1;
            CP16(d + 0*ARR_BYTES,      Ahi + ao);
            CP16(d + 0*ARR_BYTES + 16, Ahi + ao + 8);
            CP16(d + 1*ARR_BYTES,      Alo + ao);
            CP16(d + 1*ARR_BYTES + 16, Alo + ao + 8);
            CP16(d + 2*ARR_BYTES,      Bhi + bo);
            CP16(d + 2*ARR_BYTES + 16, Bhi + bo + 8);
            CP16(d + 3*ARR_BYTES,      Blo + bo);
            CP16(d + 3*ARR_BYTES + 16, Blo + bo + 8);
            CP_COMMIT();
            CP_WAIT(1);
        } else {
            CP_WAIT(0);
        }
        __syncthreads();

        const uint32_t stA_hi = smbase + cur*STAGE_BYTES + 0*ARR_BYTES;
        const uint32_t stA_lo = smbase + cur*STAGE_BYTES + 1*ARR_BYTES;
        const uint32_t stB_hi = smbase + cur*STAGE_BYTES + 2*ARR_BYTES;
        const uint32_t stB_lo = smbase + cur*STAGE_BYTES + 3*ARR_BYTES;

#pragma unroll
        for (int ks = 0; ks < 2; ks++) {
            const int koff = ks * 16;
            uint32_t afh[2][4], afl[2][4];
#pragma unroll
            for (int mi = 0; mi < 2; mi++) {
                const uint32_t off =
                    ((uint32_t)((wm*32 + mi*16 + a_row_l) * PITCH
                                + koff + a_col_l)) * 2u;
                LDSM4(afh[mi], stA_hi + off);
                LDSM4(afl[mi], stA_lo + off);
            }
#pragma unroll
            for (int jp = 0; jp < 4; jp++) {
                uint32_t bfh[4], bfl[4];
                const uint32_t off =
                    ((uint32_t)((wn*64 + jp*16 + b_n_l) * PITCH
                                + koff + b_k_l)) * 2u;
                LDSM4(bfh, stB_hi + off);
                LDSM4(bfl, stB_lo + off);
#pragma unroll
                for (int mi = 0; mi < 2; mi++) {
                    MMA16816(acc[mi][2*jp],   afh[mi], bfh[0], bfh[1]);
                    MMA16816(acc[mi][2*jp],   afh[mi], bfl[0], bfl[1]);
                    MMA16816(acc[mi][2*jp],   afl[mi], bfh[0], bfh[1]);
                    MMA16816(acc[mi][2*jp+1], afh[mi], bfh[2], bfh[3]);
                    MMA16816(acc[mi][2*jp+1], afh[mi], bfl[2], bfl[3]);
                    MMA16816(acc[mi][2*jp+1], afl[mi], bfh[2], bfh[3]);
                }
            }
        }
        __syncthreads();
    }

    const int qr = lane >> 2;
    const int qc = (lane & 3) * 2;

#pragma unroll
    for (int mi = 0; mi < 2; mi++) {
        float c[8][4];
#pragma unroll
        for (int nj = 0; nj < 8; nj++) {
            const float b0 = bias[n0 + wn*64 + nj*8 + qc];
            const float b1 = bias[n0 + wn*64 + nj*8 + qc + 1];
            c[nj][0] = acc[mi][nj][0] + b0;
            c[nj][1] = acc[mi][nj][1] + b1;
            c[nj][2] = acc[mi][nj][2] + b0;
            c[nj][3] = acc[mi][nj][3] + b1;
        }
        if (norm) {
            float ss0 = 0.f, ss1 = 0.f;
#pragma unroll
            for (int nj = 0; nj < 8; nj++) {
                ss0 += c[nj][0]*c[nj][0] + c[nj][1]*c[nj][1];
                ss1 += c[nj][2]*c[nj][2] + c[nj][3]*c[nj][3];
            }
            ss0 += __shfl_xor_sync(0xffffffffu, ss0, 1);
            ss0 += __shfl_xor_sync(0xffffffffu, ss0, 2);
            ss1 += __shfl_xor_sync(0xffffffffu, ss1, 1);
            ss1 += __shfl_xor_sync(0xffffffffu, ss1, 2);
            const float inv0 = 1.0f / fmaxf(sqrtf(ss0), 1e-12f);
            const float inv1 = 1.0f / fmaxf(sqrtf(ss1), 1e-12f);
#pragma unroll
            for (int nj = 0; nj < 8; nj++) {
                c[nj][0] *= inv0; c[nj][1] *= inv0;
                c[nj][2] *= inv1; c[nj][3] *= inv1;
            }
        }
        const int row_lo = m0 + wm*32 + mi*16 + qr;
#pragma unroll
        for (int nj = 0; nj < 8; nj++) {
            const int col = n0 + wn*64 + nj*8 + qc;
            float2 lo; lo.x = c[nj][0]; lo.y = c[nj][1];
            float2 hi; hi.x = c[nj][2]; hi.y = c[nj][3];
            *(float2*)(C + (size_t)row_lo       * N + col) = lo;
            *(float2*)(C + (size_t)(row_lo + 8) * N + col) = hi;
        }
    }
}

__global__ __launch_bounds__(256, 2) void gemm_bf16_qkv_kernel(
    const float* __restrict__ bq, const float* __restrict__ bk,
    const float* __restrict__ bv)
{
    const int z = blockIdx.z;
    const __nv_bfloat16* Wh = g_Whi + (size_t)z*HIDDEN*HIDDEN;
    const __nv_bfloat16* Wl = g_Wlo + (size_t)z*HIDDEN*HIDDEN;
    const float* bias; float* out; bool norm;
    if (z == 0)      { bias = bq; out = g_q; norm = true;  }
    else if (z == 1) { bias = bk; out = g_k; norm = true;  }
    else             { bias = bv; out = g_v; norm = false; }
    gemm_bf16_body(g_Xhi, g_Xlo, Wh, Wl, bias, out,
                   blockIdx.y * 128, blockIdx.x * 128, norm);
}

__global__ __launch_bounds__(256, 2) void gemm_bf16_out_kernel(
    const float* __restrict__ bo, float* __restrict__ C)
{
    gemm_bf16_body(g_Ohi, g_Olo,
                   g_Whi + (size_t)3*HIDDEN*HIDDEN,
                   g_Wlo + (size_t)3*HIDDEN*HIDDEN,
                   bo, C, blockIdx.y * 128, blockIdx.x * 128, false);
}

// ---------------------------------------------------------------------------
// Sequential delta-rule scan: 256 threads / (b,h), quarter-split state.
// warp w (0..7), lane l: column c = 8w + (l&7), quarter g = l>>3, rb = 16g.
// Thread owns Sc[i]=S[rb+i][c] and Sr[j]=S[c][rb+j] (16 elements each).
// The 4 quarters of column c sit at lanes l, l^8, l^16, l^24 of ONE warp, so
// all partial combines are two shfl_xor (8 then 16) — no shared partials.
// One block-wide barrier per step (__syncthreads_or for the cap test), which
// also orders the dsh/ksh/qsh publishes. Lazy 0.9 scale p as before.
// ---------------------------------------------------------------------------
__device__ __forceinline__ float clip1(float x) {
    return fminf(fmaxf(x, -CLAMP_F), CLAMP_F);
}

__device__ __forceinline__ float quad_sum(float x) {
    x += __shfl_xor_sync(0xffffffffu, x, 8);
    x += __shfl_xor_sync(0xffffffffu, x, 16);
    return x;
}

__global__ __launch_bounds__(256) void scan_kernel(float* __restrict__ state_out)
{
    __shared__ float ksh[2][HEAD_DIM];
    __shared__ float qsh[2][HEAD_DIM];
    __shared__ float dsh[2][HEAD_DIM];

    const int tid  = threadIdx.x;
    const int lane = tid & 31;
    const int w    = tid >> 5;
    const int c    = (w << 3) | (lane & 7);    // column / row index 0..63
    const int g    = lane >> 3;                // quarter 0..3
    const int rb   = g * 16;
    const int bh   = blockIdx.x;
    const size_t base = (size_t)(bh >> 4) * SEQ * HIDDEN
                      + (size_t)(bh & 15) * HEAD_DIM + c;

    float Sc[16], Sr[16];
#pragma unroll
    for (int i = 0; i < 16; i++) { Sc[i] = 0.f; Sr[i] = 0.f; }

    // stage step 0: g0 loads k, g1 loads q
    if (g == 0)      ksh[0][c] = g_k[base];
    else if (g == 1) qsh[0][c] = g_q[base];
    float kA = (g == 0) ? g_k[base + HIDDEN]
             : (g == 1) ? g_q[base + HIDDEN] : 0.f;
    float kB = 0.f;
    float vC = g_v[base];
    float vA = g_v[base + HIDDEN];
    float vB = 0.f;
    float voldraw = 0.f;
    float p = 1.f;
    __syncthreads();

    for (int s = 0; s < SEQ; s++) {
        const int cur = s & 1;
        const int nxt = cur ^ 1;

        // prefetch step s+2 (full step of latency cover)
        if (s + 2 < SEQ) {
            const size_t b2 = base + (size_t)(s + 2) * HIDDEN;
            if (g == 0)      kB = g_k[b2];
            else if (g == 1) kB = g_q[b2];
            vB = g_v[b2];
        }

        // preA: bd, publish delta, column update + lmax, stage next k/q
        const float bd = BETA_F * clip1(vC - p * voldraw);
        if (g == 0) dsh[cur][c] = bd;
        float lmax = 0.f;
        {
            const float4* kc = (const float4*)&ksh[cur][rb];
            if (p == 1.f) {
#pragma unroll
                for (int cc = 0; cc < 4; cc++) {
                    const float4 k4 = kc[cc];
                    float x0=fmaf(bd,k4.x,Sc[cc*4+0]), x1=fmaf(bd,k4.y,Sc[cc*4+1]);
                    float x2=fmaf(bd,k4.z,Sc[cc*4+2]), x3=fmaf(bd,k4.w,Sc[cc*4+3]);
                    Sc[cc*4+0]=x0; Sc[cc*4+1]=x1; Sc[cc*4+2]=x2; Sc[cc*4+3]=x3;
                    lmax = fmaxf(lmax, fmaxf(fmaxf(fabsf(x0),fabsf(x1)),
                                             fmaxf(fabsf(x2),fabsf(x3))));
                }
            } else {
#pragma unroll
                for (int cc = 0; cc < 4; cc++) {
                    const float4 k4 = kc[cc];
                    float x0=fmaf(p,Sc[cc*4+0],bd*k4.x), x1=fmaf(p,Sc[cc*4+1],bd*k4.y);
                    float x2=fmaf(p,Sc[cc*4+2],bd*k4.z), x3=fmaf(p,Sc[cc*4+3],bd*k4.w);
                    Sc[cc*4+0]=x0; Sc[cc*4+1]=x1; Sc[cc*4+2]=x2; Sc[cc*4+3]=x3;
                    lmax = fmaxf(lmax, fmaxf(fmaxf(fabsf(x0),fabsf(x1)),
                                             fmaxf(fabsf(x2),fabsf(x3))));
                }
            }
        }
        if (s + 1 < SEQ) {
            if (g == 0)      ksh[nxt][c] = kA;
            else if (g == 1) qsh[nxt][c] = kA;
        }

        const int over = __syncthreads_or(lmax > STATE_CAP_F);   // the barrier
        const float pn = over ? 0.9f : 1.0f;

        // postA: row update from shared delta + o partial from row copy
        float osum;
        {
            const float kt = ksh[cur][c];
            const float4* d4  = (const float4*)&dsh[cur][rb];
            const float4* qc4 = (const float4*)&qsh[cur][rb];
            float o0=0.f,o1=0.f,o2=0.f,o3=0.f;
            if (p == 1.f) {
#pragma unroll
                for (int cc = 0; cc < 4; cc++) {
                    const float4 dd = d4[cc];
                    float y0=fmaf(kt,dd.x,Sr[cc*4+0]), y1=fmaf(kt,dd.y,Sr[cc*4+1]);
                    float y2=fmaf(kt,dd.z,Sr[cc*4+2]), y3=fmaf(kt,dd.w,Sr[cc*4+3]);
                    Sr[cc*4+0]=y0; Sr[cc*4+1]=y1; Sr[cc*4+2]=y2; Sr[cc*4+3]=y3;
                    const float4 q4 = qc4[cc];
                    o0 += y0*q4.x; o1 += y1*q4.y;
                    o2 += y2*q4.z; o3 += y3*q4.w;
                }
            } else {
#pragma unroll
                for (int cc = 0; cc < 4; cc++) {
                    const float4 dd = d4[cc];
                    float y0=fmaf(p,Sr[cc*4+0],kt*dd.x), y1=fmaf(p,Sr[cc*4+1],kt*dd.y);
                    float y2=fmaf(p,Sr[cc*4+2],kt*dd.z), y3=fmaf(p,Sr[cc*4+3],kt*dd.w);
                    Sr[cc*4+0]=y0; Sr[cc*4+1]=y1; Sr[cc*4+2]=y2; Sr[cc*4+3]=y3;
                    const float4 q4 = qc4[cc];
                    o0 += y0*q4.x; o1 += y1*q4.y;
                    o2 += y2*q4.z; o3 += y3*q4.w;
                }
            }
            osum = quad_sum((o0+o1)+(o2+o3));
        }
        if (g == 0) {
            const float val = clip1(pn * osum);
            __nv_bfloat16 h, l;
            bf16_split1(val, h, l);
            const size_t idx = base + (size_t)s * HIDDEN;
            g_Ohi[idx] = h; g_Olo[idx] = l;
        }

        // pd for step s+1 from the column copy; combine in-warp
        if (s + 1 < SEQ) {
            const float4* kn = (const float4*)&ksh[nxt][rb];
            float d0=0.f,d1=0.f,d2=0.f,d3=0.f;
#pragma unroll
            for (int cc = 0; cc < 4; cc++) {
                const float4 k4 = kn[cc];
                d0 += k4.x*Sc[cc*4+0]; d1 += k4.y*Sc[cc*4+1];
                d2 += k4.z*Sc[cc*4+2]; d3 += k4.w*Sc[cc*4+3];
            }
            voldraw = quad_sum((d0+d1)+(d2+d3));
        }

        p  = pn;
        vC = vA; vA = vB; kA = kB;
    }

    // final true state = p * raw column copy : state_out[b][h][d][e]
    float* sp = state_out + (size_t)bh * HEAD_DIM * HEAD_DIM;
#pragma unroll
    for (int i = 0; i < 16; i++)
        sp[(rb + i) * HEAD_DIM + c] = p * Sc[i];
}

// ---------------------------------------------------------------------------
extern "C" void kernel_launch(void* const* d_in, const int* in_sizes, int n_in,
                              void* d_out, int out_size)
{
    (void)in_sizes; (void)n_in;
    const float* x  = (const float*)d_in[0];
    const float* Wq = (const float*)d_in[1];
    const float* bq = (const float*)d_in[2];
    const float* Wk = (const float*)d_in[3];
    const float* bk = (const float*)d_in[4];
    const float* Wv = (const float*)d_in[5];
    const float* bv = (const float*)d_in[6];
    const float* Wo = (const float*)d_in[7];
    const float* bo = (const float*)d_in[8];

    const int OUT_ELEMS   = ROWS * HIDDEN;
    const int STATE_ELEMS = BATCH * HEADS * HEAD_DIM * HEAD_DIM;

    float* state_out;
    if (out_size >= OUT_ELEMS + STATE_ELEMS) {
        state_out = (float*)d_out + OUT_ELEMS;
    } else {
        cudaGetSymbolAddress((void**)&state_out, g_state_scratch);
    }

    static bool attr_done = false;
    if (!attr_done) {
        cudaFuncSetAttribute(gemm_bf16_qkv_kernel,
                             cudaFuncAttributeMaxDynamicSharedMemorySize,
                             SMEM_TOTAL_B);
        cudaFuncSetAttribute(gemm_bf16_out_kernel,
                             cudaFuncAttributeMaxDynamicSharedMemorySize,
                             SMEM_TOTAL_B);
        attr_done = true;
    }

    // 0) pre-split X and all four weights to bf16 hi/lo
    dim3 gs(ROWS * HIDDEN / 8 / 256, 1, 5);
    split_kernel<<<gs, 256>>>(x, Wq, Wk, Wv, Wo);

    // 1) QKV projections (tensor-core bf16x3, cp.async, 2 CTAs/SM) + norm
    dim3 gq(HIDDEN / 128, ROWS / 128, 3);
    gemm_bf16_qkv_kernel<<<gq, 256, SMEM_TOTAL_B>>>(bq, bk, bv);

    // 2) sequential delta-rule scan (256 threads, quarter-split, 1 barrier)
    scan_kernel<<<BATCH * HEADS, 256>>>(state_out);

    // 3) output projection -> d_out
    dim3 go(HIDDEN / 128, ROWS / 128);
    gemm_bf16_out_kernel<<<go, 256, SMEM_TOTAL_B>>>(bo, (float*)d_out);
}

// round 15
// speedup vs baseline: 1.6777x; 1.6777x over previous
#include <cuda_runtime.h>
#include <cuda_bf16.h>
#include <cstdint>

#define HIDDEN    1024
#define HEADS     16
#define HEAD_DIM  64
#define BATCH     4
#define SEQ       1024
#define ROWS      (BATCH*SEQ)        // 4096
#define BETA_F    0.9f
#define CLAMP_F   1.0f
#define STATE_CAP_F 10.0f
#define PITCH     40                 // ushorts per smem row (80 B, bank-clean)

#define ARR_BYTES    (128*PITCH*2)   // 10240
#define STAGE_BYTES  (4*ARR_BYTES)   // 40960
#define SMEM_TOTAL_B (2*STAGE_BYTES) // 81920

// ---------------- scratch (static device arrays are allowed) ---------------
__device__ float g_q[ROWS*HIDDEN];
__device__ float g_k[ROWS*HIDDEN];
__device__ float g_v[ROWS*HIDDEN];
__device__ float g_state_scratch[BATCH*HEADS*HEAD_DIM*HEAD_DIM];

// pre-split bf16 operands
__device__ __nv_bfloat16 g_Xhi[ROWS*HIDDEN],  g_Xlo[ROWS*HIDDEN];
__device__ __nv_bfloat16 g_Whi[4*HIDDEN*HIDDEN], g_Wlo[4*HIDDEN*HIDDEN]; // q,k,v,o
__device__ __nv_bfloat16 g_Ohi[ROWS*HIDDEN],  g_Olo[ROWS*HIDDEN];

// ---------------------------------------------------------------------------
#define MMA16816(d, a, b0, b1)                                              \
    asm volatile("mma.sync.aligned.m16n8k16.row.col.f32.bf16.bf16.f32 "     \
                 "{%0,%1,%2,%3}, {%4,%5,%6,%7}, {%8,%9}, {%0,%1,%2,%3};"    \
                 : "+f"((d)[0]), "+f"((d)[1]), "+f"((d)[2]), "+f"((d)[3])   \
                 : "r"((a)[0]), "r"((a)[1]), "r"((a)[2]), "r"((a)[3]),      \
                   "r"(b0), "r"(b1))

#define LDSM4(r, addr)                                                      \
    asm volatile("ldmatrix.sync.aligned.m8n8.x4.shared.b16 "                \
                 "{%0,%1,%2,%3}, [%4];"                                     \
                 : "=r"((r)[0]), "=r"((r)[1]), "=r"((r)[2]), "=r"((r)[3])   \
                 : "r"(addr))

#define CP16(dst, src)                                                      \
    asm volatile("cp.async.cg.shared.global [%0], [%1], 16;"                \
                 :: "r"(dst), "l"(src))
#define CP_COMMIT() asm volatile("cp.async.commit_group;")
#define CP_WAIT(n)  asm volatile("cp.async.wait_group %0;" :: "n"(n))

__device__ __forceinline__ void bf16_split1(float x, __nv_bfloat16& h,
                                            __nv_bfloat16& l)
{
    h = __float2bfloat16_rn(x);
    l = __float2bfloat16_rn(x - __bfloat162float(h));
}

// ---------------------------------------------------------------------------
// split fp32 -> bf16 hi/lo. z=0: X; z=1..4: Wq,Wk,Wv,Wo. 8 elems/thread.
// ---------------------------------------------------------------------------
__global__ __launch_bounds__(256) void split_kernel(
    const float* __restrict__ X,  const float* __restrict__ Wq,
    const float* __restrict__ Wk, const float* __restrict__ Wv,
    const float* __restrict__ Wo)
{
    const int z = blockIdx.z;
    const float* src; __nv_bfloat16* hi; __nv_bfloat16* lo; int n8;
    if (z == 0) { src = X;  hi = g_Xhi; lo = g_Xlo; n8 = ROWS*HIDDEN/8; }
    else {
        const float* ws[4] = {Wq, Wk, Wv, Wo};
        src = ws[z-1];
        hi = g_Whi + (size_t)(z-1)*HIDDEN*HIDDEN;
        lo = g_Wlo + (size_t)(z-1)*HIDDEN*HIDDEN;
        n8 = HIDDEN*HIDDEN/8;
    }
    const int i = blockIdx.x * 256 + threadIdx.x;
    if (i >= n8) return;
    const float4* p = (const float4*)src + 2*(size_t)i;
    float4 x0 = p[0], x1 = p[1];
    __nv_bfloat16 h[8], l[8];
    bf16_split1(x0.x, h[0], l[0]); bf16_split1(x0.y, h[1], l[1]);
    bf16_split1(x0.z, h[2], l[2]); bf16_split1(x0.w, h[3], l[3]);
    bf16_split1(x1.x, h[4], l[4]); bf16_split1(x1.y, h[5], l[5]);
    bf16_split1(x1.z, h[6], l[6]); bf16_split1(x1.w, h[7], l[7]);
    *(uint4*)(hi + 8*(size_t)i) = *(uint4*)h;
    *(uint4*)(lo + 8*(size_t)i) = *(uint4*)l;
}

// ---------------------------------------------------------------------------
// bf16x3 tensor-core GEMM (byte-identical to R12).
// ---------------------------------------------------------------------------
__device__ __forceinline__ void gemm_bf16_body(
    const __nv_bfloat16* __restrict__ Ahi, const __nv_bfloat16* __restrict__ Alo,
    const __nv_bfloat16* __restrict__ Bhi, const __nv_bfloat16* __restrict__ Blo,
    const float* __restrict__ bias, float* __restrict__ C,
    int m0, int n0, bool norm)
{
    extern __shared__ unsigned short dynsm[];
    const int N = HIDDEN, K = HIDDEN;

    const int tid  = threadIdx.x;
    const int lane = tid & 31;
    const int warp = tid >> 5;
    const int wm   = warp & 3;
    const int wn   = warp >> 2;

    const int arow = tid >> 1;
    const int acol = (tid & 1) * 16;
    const size_t aoff0 = (size_t)(m0 + arow) * K + acol;
    const size_t boff0 = (size_t)(n0 + arow) * K + acol;
    const uint32_t smbase = (uint32_t)__cvta_generic_to_shared(dynsm);
    const uint32_t dst0   = smbase + (uint32_t)(arow * (PITCH*2) + (tid & 1) * 32);

    const int a_row_l = lane & 15;
    const int a_col_l = (lane >> 4) << 3;
    const int b_n_l   = ((lane >> 4) << 3) + (lane & 7);
    const int b_k_l   = ((lane >> 3) & 1) << 3;

    float acc[2][8][4];
#pragma unroll
    for (int mi = 0; mi < 2; mi++)
#pragma unroll
        for (int nj = 0; nj < 8; nj++)
#pragma unroll
            for (int r = 0; r < 4; r++) acc[mi][nj][r] = 0.f;

    {
        const uint32_t d = dst0;
        CP16(d + 0*ARR_BYTES,      Ahi + aoff0);
        CP16(d + 0*ARR_BYTES + 16, Ahi + aoff0 + 8);
        CP16(d + 1*ARR_BYTES,      Alo + aoff0);
        CP16(d + 1*ARR_BYTES + 16, Alo + aoff0 + 8);
        CP16(d + 2*ARR_BYTES,      Bhi + boff0);
        CP16(d + 2*ARR_BYTES + 16, Bhi + boff0 + 8);
        CP16(d + 3*ARR_BYTES,      Blo + boff0);
        CP16(d + 3*ARR_BYTES + 16, Blo + boff0 + 8);
        CP_COMMIT();
    }

    const int NT = K / 32;
    for (int it = 0; it < NT; it++) {
        const int cur = it & 1;
        const int nxt = cur ^ 1;
        const bool hn = (it + 1) < NT;

        if (hn) {
            const int k1 = (it + 1) * 32;
            const uint32_t d = dst0 + nxt * STAGE_BYTES;
            const size_t ao = aoff0 + k1;
            const size_t bo = boff0 + k1;
            CP16(d + 0*ARR_BYTES,      Ahi + ao);
            CP16(d + 0*ARR_BYTES + 16, Ahi + ao + 8);
            CP16(d + 1*ARR_BYTES,      Alo + ao);
            CP16(d + 1*ARR_BYTES + 16, Alo + ao + 8);
            CP16(d + 2*ARR_BYTES,      Bhi + bo);
            CP16(d + 2*ARR_BYTES + 16, Bhi + bo + 8);
            CP16(d + 3*ARR_BYTES,      Blo + bo);
            CP16(d + 3*ARR_BYTES + 16, Blo + bo + 8);
            CP_COMMIT();
            CP_WAIT(1);
        } else {
            CP_WAIT(0);
        }
        __syncthreads();

        const uint32_t stA_hi = smbase + cur*STAGE_BYTES + 0*ARR_BYTES;
        const uint32_t stA_lo = smbase + cur*STAGE_BYTES + 1*ARR_BYTES;
        const uint32_t stB_hi = smbase + cur*STAGE_BYTES + 2*ARR_BYTES;
        const uint32_t stB_lo = smbase + cur*STAGE_BYTES + 3*ARR_BYTES;

#pragma unroll
        for (int ks = 0; ks < 2; ks++) {
            const int koff = ks * 16;
            uint32_t afh[2][4], afl[2][4];
#pragma unroll
            for (int mi = 0; mi < 2; mi++) {
                const uint32_t off =
                    ((uint32_t)((wm*32 + mi*16 + a_row_l) * PITCH
                                + koff + a_col_l)) * 2u;
                LDSM4(afh[mi], stA_hi + off);
                LDSM4(afl[mi], stA_lo + off);
            }
#pragma unroll
            for (int jp = 0; jp < 4; jp++) {
                uint32_t bfh[4], bfl[4];
                const uint32_t off =
                    ((uint32_t)((wn*64 + jp*16 + b_n_l) * PITCH
                                + koff + b_k_l)) * 2u;
                LDSM4(bfh, stB_hi + off);
                LDSM4(bfl, stB_lo + off);
#pragma unroll
                for (int mi = 0; mi < 2; mi++) {
                    MMA16816(acc[mi][2*jp],   afh[mi], bfh[0], bfh[1]);
                    MMA16816(acc[mi][2*jp],   afh[mi], bfl[0], bfl[1]);
                    MMA16816(acc[mi][2*jp],   afl[mi], bfh[0], bfh[1]);
                    MMA16816(acc[mi][2*jp+1], afh[mi], bfh[2], bfh[3]);
                    MMA16816(acc[mi][2*jp+1], afh[mi], bfl[2], bfl[3]);
                    MMA16816(acc[mi][2*jp+1], afl[mi], bfh[2], bfh[3]);
                }
            }
        }
        __syncthreads();
    }

    const int qr = lane >> 2;
    const int qc = (lane & 3) * 2;

#pragma unroll
    for (int mi = 0; mi < 2; mi++) {
        float c[8][4];
#pragma unroll
        for (int nj = 0; nj < 8; nj++) {
            const float b0 = bias[n0 + wn*64 + nj*8 + qc];
            const float b1 = bias[n0 + wn*64 + nj*8 + qc + 1];
            c[nj][0] = acc[mi][nj][0] + b0;
            c[nj][1] = acc[mi][nj][1] + b1;
            c[nj][2] = acc[mi][nj][2] + b0;
            c[nj][3] = acc[mi][nj][3] + b1;
        }
        if (norm) {
            float ss0 = 0.f, ss1 = 0.f;
#pragma unroll
            for (int nj = 0; nj < 8; nj++) {
                ss0 += c[nj][0]*c[nj][0] + c[nj][1]*c[nj][1];
                ss1 += c[nj][2]*c[nj][2] + c[nj][3]*c[nj][3];
            }
            ss0 += __shfl_xor_sync(0xffffffffu, ss0, 1);
            ss0 += __shfl_xor_sync(0xffffffffu, ss0, 2);
            ss1 += __shfl_xor_sync(0xffffffffu, ss1, 1);
            ss1 += __shfl_xor_sync(0xffffffffu, ss1, 2);
            const float inv0 = 1.0f / fmaxf(sqrtf(ss0), 1e-12f);
            const float inv1 = 1.0f / fmaxf(sqrtf(ss1), 1e-12f);
#pragma unroll
            for (int nj = 0; nj < 8; nj++) {
                c[nj][0] *= inv0; c[nj][1] *= inv0;
                c[nj][2] *= inv1; c[nj][3] *= inv1;
            }
        }
        const int row_lo = m0 + wm*32 + mi*16 + qr;
#pragma unroll
        for (int nj = 0; nj < 8; nj++) {
            const int col = n0 + wn*64 + nj*8 + qc;
            float2 lo; lo.x = c[nj][0]; lo.y = c[nj][1];
            float2 hi; hi.x = c[nj][2]; hi.y = c[nj][3];
            *(float2*)(C + (size_t)row_lo       * N + col) = lo;
            *(float2*)(C + (size_t)(row_lo + 8) * N + col) = hi;
        }
    }
}

__global__ __launch_bounds__(256, 2) void gemm_bf16_qkv_kernel(
    const float* __restrict__ bq, const float* __restrict__ bk,
    const float* __restrict__ bv)
{
    const int z = blockIdx.z;
    const __nv_bfloat16* Wh = g_Whi + (size_t)z*HIDDEN*HIDDEN;
    const __nv_bfloat16* Wl = g_Wlo + (size_t)z*HIDDEN*HIDDEN;
    const float* bias; float* out; bool norm;
    if (z == 0)      { bias = bq; out = g_q; norm = true;  }
    else if (z == 1) { bias = bk; out = g_k; norm = true;  }
    else             { bias = bv; out = g_v; norm = false; }
    gemm_bf16_body(g_Xhi, g_Xlo, Wh, Wl, bias, out,
                   blockIdx.y * 128, blockIdx.x * 128, norm);
}

__global__ __launch_bounds__(256, 2) void gemm_bf16_out_kernel(
    const float* __restrict__ bo, float* __restrict__ C)
{
    gemm_bf16_body(g_Ohi, g_Olo,
                   g_Whi + (size_t)3*HIDDEN*HIDDEN,
                   g_Wlo + (size_t)3*HIDDEN*HIDDEN,
                   bo, C, blockIdx.y * 128, blockIdx.x * 128, false);
}

// ---------------------------------------------------------------------------
// Warpgroup-specialized, software-pipelined delta-rule scan.
// 128 threads / (b,h): g0 = threads 0-63 (warps 0,1), g1 = threads 64-127.
//   g0 thread t owns FULL column t: Sc[d] = S[d][t]  (recursion + final state)
//   g1 thread t owns FULL row t:    Sr[j] = S[t][j]  (o-dot)
// Slot s: g0 does step s (vold local! -> bd -> publish dsh -> Sc update ->
// lmax); g1 simultaneously does step s-1 (Sr update from dsh + fused o-dot,
// both fully local). ONE __syncthreads_or per slot orders everything.
// k/q staged in an 8-deep ring (step-m data: written slot m-3, read slots
// m (g0) / m+1 (g1) -> no buffer overlap). delta double-buffered.
// Scale history: pA = pn_{s-1}, pB = pn_{s-2}, updated identically in all
// threads from the sync result. g0 folds pA; g1 folds pB and outputs pA.
// ---------------------------------------------------------------------------
__device__ __forceinline__ float clip1(float x) {
    return fminf(fmaxf(x, -CLAMP_F), CLAMP_F);
}

__global__ __launch_bounds__(128) void scan_kernel(float* __restrict__ state_out)
{
    __shared__ float ksh[8][HEAD_DIM];
    __shared__ float qsh[8][HEAD_DIM];
    __shared__ float dsh[2][HEAD_DIM];

    const int tid = threadIdx.x;
    const int t   = tid & 63;
    const int g   = tid >> 6;     // 0 = column group, 1 = row group
    const int bh  = blockIdx.x;
    const size_t base = (size_t)(bh >> 4) * SEQ * HIDDEN
                      + (size_t)(bh & 15) * HEAD_DIM + t;

    float S[64];
#pragma unroll
    for (int i = 0; i < 64; i++) S[i] = 0.f;

    // prologue: stage steps 0..2 into ring slots 0..2; load step 3 to reg
    if (g == 0) {
        ksh[0][t] = g_k[base];
        ksh[1][t] = g_k[base + HIDDEN];
        ksh[2][t] = g_k[base + 2*HIDDEN];
    } else {
        qsh[0][t] = g_q[base];
        qsh[1][t] = g_q[base + HIDDEN];
        qsh[2][t] = g_q[base + 2*HIDDEN];
    }
    float kA = (g == 0) ? g_k[base + 3*HIDDEN] : g_q[base + 3*HIDDEN];
    // v pipeline (g0 only consumes): vC = v_s, vQ1..vQ3 = next three
    float vC  = g_v[base];
    float vQ1 = g_v[base + HIDDEN];
    float vQ2 = g_v[base + 2*HIDDEN];
    float vQ3 = g_v[base + 3*HIDDEN];

    float pA = 1.f, pB = 1.f;    // pn history: pA = pn_{s-1}, pB = pn_{s-2}
    __syncthreads();

    for (int s = 0; s < SEQ; s++) {
        // top: issue global loads for step s+4
        float kN = 0.f, vN = 0.f;
        if (s + 4 < SEQ) {
            const size_t b4 = base + (size_t)(s + 4) * HIDDEN;
            kN = (g == 0) ? g_k[b4] : g_q[b4];
            vN = g_v[b4];
        }

        int over = 0;
        if (g == 0) {
            // ---- g0: step s ----
            const float4* kc = (const float4*)&ksh[s & 7][0];
            // vold fully local
            float a0 = 0.f, a1 = 0.f, a2 = 0.f, a3 = 0.f;
#pragma unroll
            for (int cc = 0; cc < 16; cc++) {
                const float4 k4 = kc[cc];
                a0 += k4.x * S[cc*4+0];
                a1 += k4.y * S[cc*4+1];
                a2 += k4.z * S[cc*4+2];
                a3 += k4.w * S[cc*4+3];
            }
            const float vold = (a0 + a1) + (a2 + a3);
            const float bd   = BETA_F * clip1(vC - pA * vold);
            dsh[s & 1][t] = bd;
            // column update (fold pA) + lmax
            float lmax = 0.f;
            if (pA == 1.f) {
#pragma unroll
                for (int cc = 0; cc < 16; cc++) {
                    const float4 k4 = kc[cc];
                    float x0=fmaf(bd,k4.x,S[cc*4+0]), x1=fmaf(bd,k4.y,S[cc*4+1]);
                    float x2=fmaf(bd,k4.z,S[cc*4+2]), x3=fmaf(bd,k4.w,S[cc*4+3]);
                    S[cc*4+0]=x0; S[cc*4+1]=x1; S[cc*4+2]=x2; S[cc*4+3]=x3;
                    lmax = fmaxf(lmax, fmaxf(fmaxf(fabsf(x0),fabsf(x1)),
                                             fmaxf(fabsf(x2),fabsf(x3))));
                }
            } else {
#pragma unroll
                for (int cc = 0; cc < 16; cc++) {
                    const float4 k4 = kc[cc];
                    float x0=fmaf(pA,S[cc*4+0],bd*k4.x), x1=fmaf(pA,S[cc*4+1],bd*k4.y);
                    float x2=fmaf(pA,S[cc*4+2],bd*k4.z), x3=fmaf(pA,S[cc*4+3],bd*k4.w);
                    S[cc*4+0]=x0; S[cc*4+1]=x1; S[cc*4+2]=x2; S[cc*4+3]=x3;
                    lmax = fmaxf(lmax, fmaxf(fmaxf(fabsf(x0),fabsf(x1)),
                                             fmaxf(fabsf(x2),fabsf(x3))));
                }
            }
            over = (lmax > STATE_CAP_F);
            // stage k for step s+3 (kA loaded a full slot ago)
            if (s + 3 < SEQ) ksh[(s + 3) & 7][t] = kA;
        } else if (s >= 1) {
            // ---- g1: step m = s-1 ----
            const int m = s - 1;
            const float kt = ksh[m & 7][t];
            const float4* d4 = (const float4*)&dsh[m & 1][0];
            const float4* q4 = (const float4*)&qsh[m & 7][0];
            float o0 = 0.f, o1 = 0.f, o2 = 0.f, o3 = 0.f;
            if (pB == 1.f) {
#pragma unroll
                for (int cc = 0; cc < 16; cc++) {
                    const float4 dd = d4[cc];
                    float y0=fmaf(kt,dd.x,S[cc*4+0]), y1=fmaf(kt,dd.y,S[cc*4+1]);
                    float y2=fmaf(kt,dd.z,S[cc*4+2]), y3=fmaf(kt,dd.w,S[cc*4+3]);
                    S[cc*4+0]=y0; S[cc*4+1]=y1; S[cc*4+2]=y2; S[cc*4+3]=y3;
                    const float4 qq = q4[cc];
                    o0 += y0*qq.x; o1 += y1*qq.y;
                    o2 += y2*qq.z; o3 += y3*qq.w;
                }
            } else {
#pragma unroll
                for (int cc = 0; cc < 16; cc++) {
                    const float4 dd = d4[cc];
                    float y0=fmaf(pB,S[cc*4+0],kt*dd.x), y1=fmaf(pB,S[cc*4+1],kt*dd.y);
                    float y2=fmaf(pB,S[cc*4+2],kt*dd.z), y3=fmaf(pB,S[cc*4+3],kt*dd.w);
                    S[cc*4+0]=y0; S[cc*4+1]=y1; S[cc*4+2]=y2; S[cc*4+3]=y3;
                    const float4 qq = q4[cc];
                    o0 += y0*qq.x; o1 += y1*qq.y;
                    o2 += y2*qq.z; o3 += y3*qq.w;
                }
            }
            const float val = clip1(pA * ((o0 + o1) + (o2 + o3)));
            __nv_bfloat16 h, l;
            bf16_split1(val, h, l);
            const size_t idx = base + (size_t)m * HIDDEN;
            g_Ohi[idx] = h; g_Olo[idx] = l;
            if (s + 3 < SEQ) qsh[(s + 3) & 7][t] = kA;
        } else {
            if (s + 3 < SEQ) qsh[(s + 3) & 7][t] = kA;
        }

        const int overAll = __syncthreads_or(over);         // the one barrier
        const float pn = overAll ? 0.9f : 1.0f;
        pB = pA; pA = pn;

        // roll pipelines
        kA = kN;
        vC = vQ1; vQ1 = vQ2; vQ2 = vQ3; vQ3 = vN;
    }

    if (g == 1) {
        // epilogue: step SEQ-1 row update + o (delta published before the
        // last in-loop barrier). Fold scale = pB, output scale = pA.
        const int m = SEQ - 1;
        const float kt = ksh[m & 7][t];
        const float4* d4 = (const float4*)&dsh[m & 1][0];
        const float4* q4 = (const float4*)&qsh[m & 7][0];
        float o0 = 0.f, o1 = 0.f, o2 = 0.f, o3 = 0.f;
#pragma unroll
        for (int cc = 0; cc < 16; cc++) {
            const float4 dd = d4[cc];
            float y0=fmaf(pB,S[cc*4+0],kt*dd.x), y1=fmaf(pB,S[cc*4+1],kt*dd.y);
            float y2=fmaf(pB,S[cc*4+2],kt*dd.z), y3=fmaf(pB,S[cc*4+3],kt*dd.w);
            const float4 qq = q4[cc];
            o0 += y0*qq.x; o1 += y1*qq.y;
            o2 += y2*qq.z; o3 += y3*qq.w;
        }
        const float val = clip1(pA * ((o0 + o1) + (o2 + o3)));
        __nv_bfloat16 h, l;
        bf16_split1(val, h, l);
        const size_t idx = base + (size_t)m * HIDDEN;
        g_Ohi[idx] = h; g_Olo[idx] = l;
    } else {
        // final true state = pA * raw Sc : state_out[b][h][d][e], column t
        float* sp = state_out + (size_t)bh * HEAD_DIM * HEAD_DIM + t;
#pragma unroll
        for (int d = 0; d < 64; d++)
            sp[d * HEAD_DIM] = pA * S[d];
    }
}

// ---------------------------------------------------------------------------
extern "C" void kernel_launch(void* const* d_in, const int* in_sizes, int n_in,
                              void* d_out, int out_size)
{
    (void)in_sizes; (void)n_in;
    const float* x  = (const float*)d_in[0];
    const float* Wq = (const float*)d_in[1];
    const float* bq = (const float*)d_in[2];
    const float* Wk = (const float*)d_in[3];
    const float* bk = (const float*)d_in[4];
    const float* Wv = (const float*)d_in[5];
    const float* bv = (const float*)d_in[6];
    const float* Wo = (const float*)d_in[7];
    const float* bo = (const float*)d_in[8];

    const int OUT_ELEMS   = ROWS * HIDDEN;
    const int STATE_ELEMS = BATCH * HEADS * HEAD_DIM * HEAD_DIM;

    float* state_out;
    if (out_size >= OUT_ELEMS + STATE_ELEMS) {
        state_out = (float*)d_out + OUT_ELEMS;
    } else {
        cudaGetSymbolAddress((void**)&state_out, g_state_scratch);
    }

    static bool attr_done = false;
    if (!attr_done) {
        cudaFuncSetAttribute(gemm_bf16_qkv_kernel,
                             cudaFuncAttributeMaxDynamicSharedMemorySize,
                             SMEM_TOTAL_B);
        cudaFuncSetAttribute(gemm_bf16_out_kernel,
                             cudaFuncAttributeMaxDynamicSharedMemorySize,
                             SMEM_TOTAL_B);
        attr_done = true;
    }

    // 0) pre-split X and all four weights to bf16 hi/lo
    dim3 gs(ROWS * HIDDEN / 8 / 256, 1, 5);
    split_kernel<<<gs, 256>>>(x, Wq, Wk, Wv, Wo);

    // 1) QKV projections (tensor-core bf16x3, cp.async, 2 CTAs/SM) + norm
    dim3 gq(HIDDEN / 128, ROWS / 128, 3);
    gemm_bf16_qkv_kernel<<<gq, 256, SMEM_TOTAL_B>>>(bq, bk, bv);

    // 2) warpgroup-specialized pipelined scan (1 barrier/step)
    scan_kernel<<<BATCH * HEADS, 128>>>(state_out);

    // 3) output projection -> d_out
    dim3 go(HIDDEN / 128, ROWS / 128);
    gemm_bf16_out_kernel<<<go, 256, SMEM_TOTAL_B>>>(bo, (float*)d_out);
}